// round 7
// baseline (speedup 1.0000x reference)
#include <cuda_runtime.h>
#include <math_constants.h>
#include <stdint.h>

#define BD   4
#define SEQ  2048
#define EMB  1024
#define NH   16
#define HD   64
#define MROWS (BD*SEQ)   // 8192
#define SW   136         // smem row stride in words (GEMM): conflict-free frags

// Scratch (allocation-free: __device__ globals)
static __device__ float g_q  [(size_t)BD*NH*SEQ*HD];   // (B,H,S,D)
static __device__ float g_k  [(size_t)BD*NH*SEQ*HD];
static __device__ float g_v  [(size_t)BD*NH*SEQ*HD];
static __device__ float g_ctx[(size_t)BD*SEQ*EMB];     // (B,S,E)

__device__ __forceinline__ uint32_t f2tf32(float x) {
    uint32_t r;
    asm("cvt.rna.tf32.f32 %0, %1;" : "=r"(r) : "f"(x));
    return r;
}
// D = A(16x8, row) * B(8x8, col) + D, tf32 inputs, f32 accum. sm_80+ PTX.
__device__ __forceinline__ void mma_tf32(float* c, const uint32_t* a, const uint32_t* b) {
    asm volatile(
        "mma.sync.aligned.m16n8k8.row.col.f32.tf32.tf32.f32 "
        "{%0,%1,%2,%3}, {%4,%5,%6,%7}, {%8,%9}, {%0,%1,%2,%3};\n"
        : "+f"(c[0]), "+f"(c[1]), "+f"(c[2]), "+f"(c[3])
        : "r"(a[0]), "r"(a[1]), "r"(a[2]), "r"(a[3]), "r"(b[0]), "r"(b[1]));
}

// ===========================================================================
// tf32 mma.sync GEMM (unchanged from passing R6 kernel).
// ===========================================================================
template <int EPI>
__global__ void __launch_bounds__(256) gemm_tf32_mma(
    const float* __restrict__ A, const float* __restrict__ Bw,
    const float* __restrict__ bias, float* __restrict__ C)
{
    __shared__ uint32_t sA[2][16 * SW];
    __shared__ uint32_t sB[2][16 * SW];

    const int t  = threadIdx.x;
    const int bm = blockIdx.y * 128;
    const int bn = blockIdx.x * 128;

    const int lm = t >> 1;            // 0..127
    const int kq = (t & 1) * 8;       // 0 or 8
    const float* Ap = A  + (size_t)(bm + lm) * EMB + kq;
    const float* Bp = Bw + (size_t)(bn + lm) * EMB + kq;

    const int wid  = t >> 5, lane = t & 31;
    const int q    = lane & 3, g = lane >> 2;
    const int wm   = (wid & 1) * 64;
    const int wn   = (wid >> 1) * 32;

    float acc[4][4][4] = {};

    auto stage = [&](int buf, float4 a0, float4 a1, float4 b0, float4 b1) {
        uint32_t* pa = &sA[buf][lm];
        uint32_t* pb = &sB[buf][lm];
        pa[(kq+0)*SW] = f2tf32(a0.x); pa[(kq+1)*SW] = f2tf32(a0.y);
        pa[(kq+2)*SW] = f2tf32(a0.z); pa[(kq+3)*SW] = f2tf32(a0.w);
        pa[(kq+4)*SW] = f2tf32(a1.x); pa[(kq+5)*SW] = f2tf32(a1.y);
        pa[(kq+6)*SW] = f2tf32(a1.z); pa[(kq+7)*SW] = f2tf32(a1.w);
        pb[(kq+0)*SW] = f2tf32(b0.x); pb[(kq+1)*SW] = f2tf32(b0.y);
        pb[(kq+2)*SW] = f2tf32(b0.z); pb[(kq+3)*SW] = f2tf32(b0.w);
        pb[(kq+4)*SW] = f2tf32(b1.x); pb[(kq+5)*SW] = f2tf32(b1.y);
        pb[(kq+6)*SW] = f2tf32(b1.z); pb[(kq+7)*SW] = f2tf32(b1.w);
    };

    {
        float4 a0 = *(const float4*)(Ap + 0), a1 = *(const float4*)(Ap + 4);
        float4 b0 = *(const float4*)(Bp + 0), b1 = *(const float4*)(Bp + 4);
        stage(0, a0, a1, b0, b1);
    }
    __syncthreads();

    int buf = 0;
    for (int c = 0; c < EMB / 16; ++c) {
        float4 na0, na1, nb0, nb1;
        const bool more = (c + 1) < EMB / 16;
        if (more) {
            const int k0 = (c + 1) * 16;
            na0 = *(const float4*)(Ap + k0 + 0); na1 = *(const float4*)(Ap + k0 + 4);
            nb0 = *(const float4*)(Bp + k0 + 0); nb1 = *(const float4*)(Bp + k0 + 4);
        }

        #pragma unroll
        for (int ks = 0; ks < 16; ks += 8) {
            const uint32_t* paq  = &sA[buf][(ks + q    ) * SW];
            const uint32_t* paq4 = &sA[buf][(ks + q + 4) * SW];
            const uint32_t* pbq  = &sB[buf][(ks + q    ) * SW];
            const uint32_t* pbq4 = &sB[buf][(ks + q + 4) * SW];

            uint32_t af[4][4], bf[4][2];
            #pragma unroll
            for (int tm = 0; tm < 4; ++tm) {
                const int mo = wm + tm * 16 + g;
                af[tm][0] = paq [mo];     af[tm][1] = paq [mo + 8];
                af[tm][2] = paq4[mo];     af[tm][3] = paq4[mo + 8];
            }
            #pragma unroll
            for (int tn = 0; tn < 4; ++tn) {
                const int no = wn + tn * 8 + g;
                bf[tn][0] = pbq [no];     bf[tn][1] = pbq4[no];
            }
            #pragma unroll
            for (int tm = 0; tm < 4; ++tm)
                #pragma unroll
                for (int tn = 0; tn < 4; ++tn)
                    mma_tf32(acc[tm][tn], af[tm], bf[tn]);
        }

        if (more) {
            stage(buf ^ 1, na0, na1, nb0, nb1);
            __syncthreads();
            buf ^= 1;
        }
    }

    #pragma unroll
    for (int tm = 0; tm < 4; ++tm) {
        const int r0 = bm + wm + tm * 16 + g;
        #pragma unroll
        for (int tn = 0; tn < 4; ++tn) {
            const int n  = bn + wn + tn * 8 + 2 * q;
            const float bx = bias[n], by = bias[n + 1];
            float2 v0 = make_float2(acc[tm][tn][0] + bx, acc[tm][tn][1] + by);
            float2 v1 = make_float2(acc[tm][tn][2] + bx, acc[tm][tn][3] + by);
            if (EPI == 0) {
                *(float2*)&C[(size_t)r0      * EMB + n] = v0;
                *(float2*)&C[(size_t)(r0+8)  * EMB + n] = v1;
            } else {
                const int h_ = n >> 6, d_ = n & (HD - 1);
                {
                    const int b_ = r0 >> 11, s_ = r0 & (SEQ - 1);
                    *(float2*)&C[((((size_t)b_ * NH + h_) * SEQ + s_) << 6) + d_] = v0;
                }
                {
                    const int r1 = r0 + 8;
                    const int b_ = r1 >> 11, s_ = r1 & (SEQ - 1);
                    *(float2*)&C[((((size_t)b_ * NH + h_) * SEQ + s_) << 6) + d_] = v1;
                }
            }
        }
    }
}

// ---------------------------------------------------------------------------
// fp32 flash attention, causal. 128 threads/CTA, 64-row Q tile.
// Each thread owns 8 rows x 4 cols (was 4x4): every 16B KV smem fragment now
// feeds 32 FMAs instead of 16 -> smem traffic per FLOP halved.
// Row-reduction pattern (width-16 shuffles) identical to the passing kernel.
// ---------------------------------------------------------------------------
__global__ void __launch_bounds__(128) flash_attn(
    const float* __restrict__ Q, const float* __restrict__ K,
    const float* __restrict__ V, float* __restrict__ ctx)
{
    __shared__ float Qs[64][64];
    __shared__ float KP[64][64];
    __shared__ float Vs[64][64];

    const int t  = threadIdx.x;         // 0..127
    const int qt = blockIdx.x;          // query tile
    const int bh = blockIdx.y;          // batch*head
    const int b_ = bh >> 4, h_ = bh & (NH - 1);

    const int lr = t >> 1;              // load row 0..63
    const int lc = (t & 1) * 32;        // load col base (8 float4 per thread)

    const float* Qg = Q + ((size_t)bh * SEQ + (size_t)qt * 64) * HD;
    #pragma unroll
    for (int v = 0; v < 8; v++) {
        float4 x = *(const float4*)(Qg + lr*HD + lc + v*4);
        x.x *= 0.125f; x.y *= 0.125f; x.z *= 0.125f; x.w *= 0.125f;
        *(float4*)&Qs[lr][lc + v*4] = x;
    }

    const int tr = t >> 4;              // 0..7
    const int tc = t & 15;              // 0..15
    const int r0 = tr * 8;              // 8 rows per thread

    float m_i[8], l_i[8], o[8][4];
    #pragma unroll
    for (int i = 0; i < 8; i++) {
        m_i[i] = -CUDART_INF_F; l_i[i] = 0.f;
        #pragma unroll
        for (int j = 0; j < 4; j++) o[i][j] = 0.f;
    }

    for (int jt = 0; jt <= qt; jt++) {
        const float* Kg = K + ((size_t)bh * SEQ + (size_t)jt * 64) * HD;
        const float* Vg = V + ((size_t)bh * SEQ + (size_t)jt * 64) * HD;

        __syncthreads();                        // prev-iter consumers done
        #pragma unroll
        for (int v = 0; v < 8; v++) {
            float4 x = *(const float4*)(Kg + lr*HD + lc + v*4);
            KP[lc + v*4 + 0][lr] = x.x;         // K^T: [d][c]
            KP[lc + v*4 + 1][lr] = x.y;
            KP[lc + v*4 + 2][lr] = x.z;
            KP[lc + v*4 + 3][lr] = x.w;
            *(float4*)&Vs[lr][lc + v*4] = *(const float4*)(Vg + lr*HD + lc + v*4);
        }
        __syncthreads();

        // S = (Q/8) * K^T  (8x4 per thread)
        float s[8][4] = {};
        #pragma unroll 4
        for (int d = 0; d < 64; d++) {
            float4 kv = *(const float4*)&KP[d][tc * 4];
            #pragma unroll
            for (int i = 0; i < 8; i++) {
                const float qv = Qs[r0 + i][d];
                s[i][0] = fmaf(qv, kv.x, s[i][0]);
                s[i][1] = fmaf(qv, kv.y, s[i][1]);
                s[i][2] = fmaf(qv, kv.z, s[i][2]);
                s[i][3] = fmaf(qv, kv.w, s[i][3]);
            }
        }

        // causal mask + online softmax (scores already scaled)
        const int rg0 = qt * 64 + r0;
        const int cg0 = jt * 64 + tc * 4;
        #pragma unroll
        for (int i = 0; i < 8; i++) {
            float rowm = -CUDART_INF_F;
            #pragma unroll
            for (int jj = 0; jj < 4; jj++) {
                float v_ = s[i][jj];
                if (cg0 + jj > rg0 + i) v_ = -CUDART_INF_F;
                s[i][jj] = v_;
                rowm = fmaxf(rowm, v_);
            }
            rowm = fmaxf(rowm, __shfl_xor_sync(0xffffffffu, rowm, 8, 16));
            rowm = fmaxf(rowm, __shfl_xor_sync(0xffffffffu, rowm, 4, 16));
            rowm = fmaxf(rowm, __shfl_xor_sync(0xffffffffu, rowm, 2, 16));
            rowm = fmaxf(rowm, __shfl_xor_sync(0xffffffffu, rowm, 1, 16));
            const float mnew = fmaxf(m_i[i], rowm);
            const float resc = __expf(m_i[i] - mnew);
            m_i[i] = mnew;
            float rs = 0.f;
            #pragma unroll
            for (int jj = 0; jj < 4; jj++) {
                s[i][jj] = __expf(s[i][jj] - mnew);
                rs += s[i][jj];
            }
            rs += __shfl_xor_sync(0xffffffffu, rs, 8, 16);
            rs += __shfl_xor_sync(0xffffffffu, rs, 4, 16);
            rs += __shfl_xor_sync(0xffffffffu, rs, 2, 16);
            rs += __shfl_xor_sync(0xffffffffu, rs, 1, 16);
            l_i[i] = l_i[i] * resc + rs;
            #pragma unroll
            for (int jj = 0; jj < 4; jj++) o[i][jj] *= resc;
        }

        __syncthreads();                        // everyone done reading KP as K^T
        float (*Ps)[64] = KP;                   // alias as P[r][c]
        #pragma unroll
        for (int i = 0; i < 8; i++)
            *(float4*)&Ps[r0 + i][tc * 4] =
                make_float4(s[i][0], s[i][1], s[i][2], s[i][3]);
        __syncthreads();

        // O += P * V  (8 rows x 4 head-dims per thread)
        #pragma unroll 4
        for (int c = 0; c < 64; c++) {
            float4 vv = *(const float4*)&Vs[c][tc * 4];
            #pragma unroll
            for (int i = 0; i < 8; i++) {
                const float pv = Ps[r0 + i][c];
                o[i][0] = fmaf(pv, vv.x, o[i][0]);
                o[i][1] = fmaf(pv, vv.y, o[i][1]);
                o[i][2] = fmaf(pv, vv.z, o[i][2]);
                o[i][3] = fmaf(pv, vv.w, o[i][3]);
            }
        }
    }

    // epilogue: normalize, write ctx in (B,S,E)
    #pragma unroll
    for (int i = 0; i < 8; i++) {
        const float inv = 1.f / l_i[i];
        const int s_ = qt * 64 + r0 + i;
        float4 r;
        r.x = o[i][0] * inv; r.y = o[i][1] * inv;
        r.z = o[i][2] * inv; r.w = o[i][3] * inv;
        *(float4*)&ctx[((size_t)b_ * SEQ + s_) * EMB + h_ * HD + tc * 4] = r;
    }
}

// ---------------------------------------------------------------------------
extern "C" void kernel_launch(void* const* d_in, const int* in_sizes, int n_in,
                              void* d_out, int out_size)
{
    (void)in_sizes; (void)n_in; (void)out_size;
    const float* query = (const float*)d_in[0];
    const float* key   = (const float*)d_in[1];
    const float* value = (const float*)d_in[2];
    // d_in[3] = attn_mask (causal triu) — baked into the flash kernel
    const float* q_w = (const float*)d_in[4];
    const float* q_b = (const float*)d_in[5];
    const float* k_w = (const float*)d_in[6];
    const float* k_b = (const float*)d_in[7];
    const float* v_w = (const float*)d_in[8];
    const float* v_b = (const float*)d_in[9];
    const float* o_w = (const float*)d_in[10];
    const float* o_b = (const float*)d_in[11];

    float *gq, *gk, *gv, *gctx;
    cudaGetSymbolAddress((void**)&gq,   g_q);
    cudaGetSymbolAddress((void**)&gk,   g_k);
    cudaGetSymbolAddress((void**)&gv,   g_v);
    cudaGetSymbolAddress((void**)&gctx, g_ctx);

    const dim3 gg(EMB / 128, MROWS / 128);   // (8, 64)
    gemm_tf32_mma<1><<<gg, 256>>>(query, q_w, q_b, gq);
    gemm_tf32_mma<1><<<gg, 256>>>(key,   k_w, k_b, gk);
    gemm_tf32_mma<1><<<gg, 256>>>(value, v_w, v_b, gv);

    flash_attn<<<dim3(SEQ / 64, BD * NH), 128>>>(gq, gk, gv, gctx);

    gemm_tf32_mma<0><<<gg, 256>>>(gctx, o_w, o_b, (float*)d_out);
}

// round 9
// speedup vs baseline: 1.0563x; 1.0563x over previous
#include <cuda_runtime.h>
#include <math_constants.h>
#include <stdint.h>

#define BD   4
#define SEQ  2048
#define EMB  1024
#define NH   16
#define HD   64
#define MROWS (BD*SEQ)   // 8192
#define SW   136         // smem row stride in words (GEMM): conflict-free frags

// Scratch (allocation-free: __device__ globals)
static __device__ float g_q  [(size_t)BD*NH*SEQ*HD];   // (B,H,S,D)
static __device__ float g_k  [(size_t)BD*NH*SEQ*HD];
static __device__ float g_v  [(size_t)BD*NH*SEQ*HD];
static __device__ float g_ctx[(size_t)BD*SEQ*EMB];     // (B,S,E)

__device__ __forceinline__ uint32_t f2tf32(float x) {
    uint32_t r;
    asm("cvt.rna.tf32.f32 %0, %1;" : "=r"(r) : "f"(x));
    return r;
}
// D = A(16x8, row) * B(8x8, col) + D, tf32 inputs, f32 accum. sm_80+ PTX.
__device__ __forceinline__ void mma_tf32(float* c, const uint32_t* a, const uint32_t* b) {
    asm volatile(
        "mma.sync.aligned.m16n8k8.row.col.f32.tf32.tf32.f32 "
        "{%0,%1,%2,%3}, {%4,%5,%6,%7}, {%8,%9}, {%0,%1,%2,%3};\n"
        : "+f"(c[0]), "+f"(c[1]), "+f"(c[2]), "+f"(c[3])
        : "r"(a[0]), "r"(a[1]), "r"(a[2]), "r"(a[3]), "r"(b[0]), "r"(b[1]));
}

// ===========================================================================
// tf32 mma.sync GEMM body (same math/layout as passing R6 kernel).
// FUSED=1: blockIdx.z in {0,1,2} selects (A,C,bias) triple; head-split out.
// FUSED=0: single GEMM, row-major out.
// ===========================================================================
template <int FUSED>
__global__ void __launch_bounds__(256) gemm_tf32_mma(
    const float* __restrict__ A0, const float* __restrict__ A1,
    const float* __restrict__ A2,
    const float* __restrict__ W0, const float* __restrict__ W1,
    const float* __restrict__ W2,
    const float* __restrict__ b0, const float* __restrict__ b1,
    const float* __restrict__ b2,
    float* __restrict__ C0, float* __restrict__ C1, float* __restrict__ C2)
{
    __shared__ uint32_t sA[2][16 * SW];
    __shared__ uint32_t sB[2][16 * SW];

    const int z = FUSED ? blockIdx.z : 0;
    const float* A    = (z == 0) ? A0 : (z == 1) ? A1 : A2;
    const float* Bw   = (z == 0) ? W0 : (z == 1) ? W1 : W2;
    const float* bias = (z == 0) ? b0 : (z == 1) ? b1 : b2;
    float*       C    = (z == 0) ? C0 : (z == 1) ? C1 : C2;

    const int t  = threadIdx.x;
    const int bm = blockIdx.y * 128;
    const int bn = blockIdx.x * 128;

    const int lm = t >> 1;            // 0..127
    const int kq = (t & 1) * 8;       // 0 or 8
    const float* Ap = A  + (size_t)(bm + lm) * EMB + kq;
    const float* Bp = Bw + (size_t)(bn + lm) * EMB + kq;

    const int wid  = t >> 5, lane = t & 31;
    const int q    = lane & 3, g = lane >> 2;
    const int wm   = (wid & 1) * 64;
    const int wn   = (wid >> 1) * 32;

    float acc[4][4][4] = {};

    auto stage = [&](int buf, float4 a0, float4 a1, float4 v0, float4 v1) {
        uint32_t* pa = &sA[buf][lm];
        uint32_t* pb = &sB[buf][lm];
        pa[(kq+0)*SW] = f2tf32(a0.x); pa[(kq+1)*SW] = f2tf32(a0.y);
        pa[(kq+2)*SW] = f2tf32(a0.z); pa[(kq+3)*SW] = f2tf32(a0.w);
        pa[(kq+4)*SW] = f2tf32(a1.x); pa[(kq+5)*SW] = f2tf32(a1.y);
        pa[(kq+6)*SW] = f2tf32(a1.z); pa[(kq+7)*SW] = f2tf32(a1.w);
        pb[(kq+0)*SW] = f2tf32(v0.x); pb[(kq+1)*SW] = f2tf32(v0.y);
        pb[(kq+2)*SW] = f2tf32(v0.z); pb[(kq+3)*SW] = f2tf32(v0.w);
        pb[(kq+4)*SW] = f2tf32(v1.x); pb[(kq+5)*SW] = f2tf32(v1.y);
        pb[(kq+6)*SW] = f2tf32(v1.z); pb[(kq+7)*SW] = f2tf32(v1.w);
    };

    {
        float4 a0 = *(const float4*)(Ap + 0), a1 = *(const float4*)(Ap + 4);
        float4 v0 = *(const float4*)(Bp + 0), v1 = *(const float4*)(Bp + 4);
        stage(0, a0, a1, v0, v1);
    }
    __syncthreads();

    int buf = 0;
    for (int c = 0; c < EMB / 16; ++c) {
        float4 na0, na1, nb0, nb1;
        const bool more = (c + 1) < EMB / 16;
        if (more) {
            const int k0 = (c + 1) * 16;
            na0 = *(const float4*)(Ap + k0 + 0); na1 = *(const float4*)(Ap + k0 + 4);
            nb0 = *(const float4*)(Bp + k0 + 0); nb1 = *(const float4*)(Bp + k0 + 4);
        }

        #pragma unroll
        for (int ks = 0; ks < 16; ks += 8) {
            const uint32_t* paq  = &sA[buf][(ks + q    ) * SW];
            const uint32_t* paq4 = &sA[buf][(ks + q + 4) * SW];
            const uint32_t* pbq  = &sB[buf][(ks + q    ) * SW];
            const uint32_t* pbq4 = &sB[buf][(ks + q + 4) * SW];

            uint32_t af[4][4], bf[4][2];
            #pragma unroll
            for (int tm = 0; tm < 4; ++tm) {
                const int mo = wm + tm * 16 + g;
                af[tm][0] = paq [mo];     af[tm][1] = paq [mo + 8];
                af[tm][2] = paq4[mo];     af[tm][3] = paq4[mo + 8];
            }
            #pragma unroll
            for (int tn = 0; tn < 4; ++tn) {
                const int no = wn + tn * 8 + g;
                bf[tn][0] = pbq [no];     bf[tn][1] = pbq4[no];
            }
            #pragma unroll
            for (int tm = 0; tm < 4; ++tm)
                #pragma unroll
                for (int tn = 0; tn < 4; ++tn)
                    mma_tf32(acc[tm][tn], af[tm], bf[tn]);
        }

        if (more) {
            stage(buf ^ 1, na0, na1, nb0, nb1);
            __syncthreads();
            buf ^= 1;
        }
    }

    #pragma unroll
    for (int tm = 0; tm < 4; ++tm) {
        const int r0 = bm + wm + tm * 16 + g;
        #pragma unroll
        for (int tn = 0; tn < 4; ++tn) {
            const int n  = bn + wn + tn * 8 + 2 * q;
            const float bx = bias[n], by = bias[n + 1];
            float2 v0 = make_float2(acc[tm][tn][0] + bx, acc[tm][tn][1] + by);
            float2 v1 = make_float2(acc[tm][tn][2] + bx, acc[tm][tn][3] + by);
            if (FUSED == 0) {
                *(float2*)&C[(size_t)r0      * EMB + n] = v0;
                *(float2*)&C[(size_t)(r0+8)  * EMB + n] = v1;
            } else {
                const int h_ = n >> 6, d_ = n & (HD - 1);
                {
                    const int b_ = r0 >> 11, s_ = r0 & (SEQ - 1);
                    *(float2*)&C[((((size_t)b_ * NH + h_) * SEQ + s_) << 6) + d_] = v0;
                }
                {
                    const int r1 = r0 + 8;
                    const int b_ = r1 >> 11, s_ = r1 & (SEQ - 1);
                    *(float2*)&C[((((size_t)b_ * NH + h_) * SEQ + s_) << 6) + d_] = v1;
                }
            }
        }
    }
}

// ---------------------------------------------------------------------------
// fp32 flash attention, causal (R6 4x4/256-thread layout — known best).
// blockIdx.x reversed: longest query tiles (most KV iters) scheduled first
// so triangular-workload stragglers start in wave 1.
// ---------------------------------------------------------------------------
__global__ void __launch_bounds__(256) flash_attn(
    const float* __restrict__ Q, const float* __restrict__ K,
    const float* __restrict__ V, float* __restrict__ ctx)
{
    __shared__ float Qs[64][64];
    __shared__ float KP[64][64];
    __shared__ float Vs[64][64];

    const int t  = threadIdx.x;
    const int qt = (SEQ / 64 - 1) - blockIdx.x;   // longest first
    const int bh = blockIdx.y;          // batch*head
    const int b_ = bh >> 4, h_ = bh & (NH - 1);

    const int lr = t >> 2;              // load row 0..63
    const int lc = (t & 3) * 16;        // load col base

    const float* Qg = Q + ((size_t)bh * SEQ + (size_t)qt * 64) * HD;
    #pragma unroll
    for (int v = 0; v < 4; v++) {
        float4 x = *(const float4*)(Qg + lr*HD + lc + v*4);
        x.x *= 0.125f; x.y *= 0.125f; x.z *= 0.125f; x.w *= 0.125f;
        *(float4*)&Qs[lr][lc + v*4] = x;
    }

    const int tr = t >> 4;              // 0..15
    const int tc = t & 15;              // 0..15
    const int r0 = tr * 4;

    float m_i[4], l_i[4], o[4][4];
    #pragma unroll
    for (int i = 0; i < 4; i++) {
        m_i[i] = -CUDART_INF_F; l_i[i] = 0.f;
        #pragma unroll
        for (int j = 0; j < 4; j++) o[i][j] = 0.f;
    }

    for (int jt = 0; jt <= qt; jt++) {
        const float* Kg = K + ((size_t)bh * SEQ + (size_t)jt * 64) * HD;
        const float* Vg = V + ((size_t)bh * SEQ + (size_t)jt * 64) * HD;

        __syncthreads();                        // prev-iter consumers done
        #pragma unroll
        for (int v = 0; v < 4; v++) {
            float4 x = *(const float4*)(Kg + lr*HD + lc + v*4);
            KP[lc + v*4 + 0][lr] = x.x;         // K^T: [d][c]
            KP[lc + v*4 + 1][lr] = x.y;
            KP[lc + v*4 + 2][lr] = x.z;
            KP[lc + v*4 + 3][lr] = x.w;
            *(float4*)&Vs[lr][lc + v*4] = *(const float4*)(Vg + lr*HD + lc + v*4);
        }
        __syncthreads();

        // S = (Q/8) * K^T  (4x4 per thread)
        float s[4][4] = {};
        #pragma unroll 8
        for (int d = 0; d < 64; d++) {
            float4 kv = *(const float4*)&KP[d][tc * 4];
            float q0 = Qs[r0+0][d], q1 = Qs[r0+1][d];
            float q2 = Qs[r0+2][d], q3 = Qs[r0+3][d];
            s[0][0] = fmaf(q0, kv.x, s[0][0]); s[0][1] = fmaf(q0, kv.y, s[0][1]);
            s[0][2] = fmaf(q0, kv.z, s[0][2]); s[0][3] = fmaf(q0, kv.w, s[0][3]);
            s[1][0] = fmaf(q1, kv.x, s[1][0]); s[1][1] = fmaf(q1, kv.y, s[1][1]);
            s[1][2] = fmaf(q1, kv.z, s[1][2]); s[1][3] = fmaf(q1, kv.w, s[1][3]);
            s[2][0] = fmaf(q2, kv.x, s[2][0]); s[2][1] = fmaf(q2, kv.y, s[2][1]);
            s[2][2] = fmaf(q2, kv.z, s[2][2]); s[2][3] = fmaf(q2, kv.w, s[2][3]);
            s[3][0] = fmaf(q3, kv.x, s[3][0]); s[3][1] = fmaf(q3, kv.y, s[3][1]);
            s[3][2] = fmaf(q3, kv.z, s[3][2]); s[3][3] = fmaf(q3, kv.w, s[3][3]);
        }

        // causal mask + online softmax (scores already scaled)
        const int rg0 = qt * 64 + r0;
        const int cg0 = jt * 64 + tc * 4;
        #pragma unroll
        for (int i = 0; i < 4; i++) {
            float rowm = -CUDART_INF_F;
            #pragma unroll
            for (int jj = 0; jj < 4; jj++) {
                float v_ = s[i][jj];
                if (cg0 + jj > rg0 + i) v_ = -CUDART_INF_F;
                s[i][jj] = v_;
                rowm = fmaxf(rowm, v_);
            }
            rowm = fmaxf(rowm, __shfl_xor_sync(0xffffffffu, rowm, 8, 16));
            rowm = fmaxf(rowm, __shfl_xor_sync(0xffffffffu, rowm, 4, 16));
            rowm = fmaxf(rowm, __shfl_xor_sync(0xffffffffu, rowm, 2, 16));
            rowm = fmaxf(rowm, __shfl_xor_sync(0xffffffffu, rowm, 1, 16));
            const float mnew = fmaxf(m_i[i], rowm);
            const float resc = __expf(m_i[i] - mnew);
            m_i[i] = mnew;
            float rs = 0.f;
            #pragma unroll
            for (int jj = 0; jj < 4; jj++) {
                s[i][jj] = __expf(s[i][jj] - mnew);
                rs += s[i][jj];
            }
            rs += __shfl_xor_sync(0xffffffffu, rs, 8, 16);
            rs += __shfl_xor_sync(0xffffffffu, rs, 4, 16);
            rs += __shfl_xor_sync(0xffffffffu, rs, 2, 16);
            rs += __shfl_xor_sync(0xffffffffu, rs, 1, 16);
            l_i[i] = l_i[i] * resc + rs;
            #pragma unroll
            for (int jj = 0; jj < 4; jj++) o[i][jj] *= resc;
        }

        __syncthreads();                        // everyone done reading KP as K^T
        float (*Ps)[64] = KP;                   // alias as P[r][c]
        #pragma unroll
        for (int i = 0; i < 4; i++)
            *(float4*)&Ps[r0 + i][tc * 4] =
                make_float4(s[i][0], s[i][1], s[i][2], s[i][3]);
        __syncthreads();

        // O += P * V  (4 rows x 4 head-dims per thread)
        #pragma unroll 8
        for (int c = 0; c < 64; c++) {
            float4 vv = *(const float4*)&Vs[c][tc * 4];
            float p0 = Ps[r0+0][c], p1 = Ps[r0+1][c];
            float p2 = Ps[r0+2][c], p3 = Ps[r0+3][c];
            o[0][0] = fmaf(p0, vv.x, o[0][0]); o[0][1] = fmaf(p0, vv.y, o[0][1]);
            o[0][2] = fmaf(p0, vv.z, o[0][2]); o[0][3] = fmaf(p0, vv.w, o[0][3]);
            o[1][0] = fmaf(p1, vv.x, o[1][0]); o[1][1] = fmaf(p1, vv.y, o[1][1]);
            o[1][2] = fmaf(p1, vv.z, o[1][2]); o[1][3] = fmaf(p1, vv.w, o[1][3]);
            o[2][0] = fmaf(p2, vv.x, o[2][0]); o[2][1] = fmaf(p2, vv.y, o[2][1]);
            o[2][2] = fmaf(p2, vv.z, o[2][2]); o[2][3] = fmaf(p2, vv.w, o[2][3]);
            o[3][0] = fmaf(p3, vv.x, o[3][0]); o[3][1] = fmaf(p3, vv.y, o[3][1]);
            o[3][2] = fmaf(p3, vv.z, o[3][2]); o[3][3] = fmaf(p3, vv.w, o[3][3]);
        }
    }

    // epilogue: normalize, write ctx in (B,S,E)
    #pragma unroll
    for (int i = 0; i < 4; i++) {
        const float inv = 1.f / l_i[i];
        const int s_ = qt * 64 + r0 + i;
        float4 r;
        r.x = o[i][0] * inv; r.y = o[i][1] * inv;
        r.z = o[i][2] * inv; r.w = o[i][3] * inv;
        *(float4*)&ctx[((size_t)b_ * SEQ + s_) * EMB + h_ * HD + tc * 4] = r;
    }
}

// ---------------------------------------------------------------------------
extern "C" void kernel_launch(void* const* d_in, const int* in_sizes, int n_in,
                              void* d_out, int out_size)
{
    (void)in_sizes; (void)n_in; (void)out_size;
    const float* query = (const float*)d_in[0];
    const float* key   = (const float*)d_in[1];
    const float* value = (const float*)d_in[2];
    // d_in[3] = attn_mask (causal triu) — baked into the flash kernel
    const float* q_w = (const float*)d_in[4];
    const float* q_b = (const float*)d_in[5];
    const float* k_w = (const float*)d_in[6];
    const float* k_b = (const float*)d_in[7];
    const float* v_w = (const float*)d_in[8];
    const float* v_b = (const float*)d_in[9];
    const float* o_w = (const float*)d_in[10];
    const float* o_b = (const float*)d_in[11];

    float *gq, *gk, *gv, *gctx;
    cudaGetSymbolAddress((void**)&gq,   g_q);
    cudaGetSymbolAddress((void**)&gk,   g_k);
    cudaGetSymbolAddress((void**)&gv,   g_v);
    cudaGetSymbolAddress((void**)&gctx, g_ctx);

    // fused Q/K/V projections: one launch, 3x grid depth
    gemm_tf32_mma<1><<<dim3(EMB / 128, MROWS / 128, 3), 256>>>(
        query, key, value,
        q_w, k_w, v_w,
        q_b, k_b, v_b,
        gq, gk, gv);

    flash_attn<<<dim3(SEQ / 64, BD * NH), 256>>>(gq, gk, gv, gctx);

    gemm_tf32_mma<0><<<dim3(EMB / 128, MROWS / 128, 1), 256>>>(
        gctx, nullptr, nullptr,
        o_w, nullptr, nullptr,
        o_b, nullptr, nullptr,
        (float*)d_out, nullptr, nullptr);
}

// round 11
// speedup vs baseline: 1.8714x; 1.7717x over previous
#include <cuda_runtime.h>
#include <math_constants.h>
#include <stdint.h>

#define BD   4
#define SEQ  2048
#define EMB  1024
#define NH   16
#define HD   64
#define MROWS (BD*SEQ)   // 8192
#define SW   136         // GEMM smem row stride in words: conflict-free frags

// Scratch (allocation-free: __device__ globals)
static __device__ float g_q  [(size_t)BD*NH*SEQ*HD];   // (B,H,S,D)
static __device__ float g_k  [(size_t)BD*NH*SEQ*HD];
static __device__ float g_v  [(size_t)BD*NH*SEQ*HD];
static __device__ float g_ctx[(size_t)BD*SEQ*EMB];     // (B,S,E)

__device__ __forceinline__ uint32_t f2tf32(float x) {
    uint32_t r;
    asm("cvt.rna.tf32.f32 %0, %1;" : "=r"(r) : "f"(x));
    return r;
}
// D = A(16x8, row) * B(8x8, col) + D, tf32 inputs, f32 accum. sm_80+ PTX.
// Fragment map (validated by working GEMM): a0=A[g][q] a1=A[g+8][q]
// a2=A[g][q+4] a3=A[g+8][q+4]; b0=B[q][g] b1=B[q+4][g]; c0=C[g][2q] c1=C[g][2q+1]
// c2=C[g+8][2q] c3=C[g+8][2q+1].   (g=lane>>2, q=lane&3)
__device__ __forceinline__ void mma_tf32(float* c, const uint32_t* a, const uint32_t* b) {
    asm volatile(
        "mma.sync.aligned.m16n8k8.row.col.f32.tf32.tf32.f32 "
        "{%0,%1,%2,%3}, {%4,%5,%6,%7}, {%8,%9}, {%0,%1,%2,%3};\n"
        : "+f"(c[0]), "+f"(c[1]), "+f"(c[2]), "+f"(c[3])
        : "r"(a[0]), "r"(a[1]), "r"(a[2]), "r"(a[3]), "r"(b[0]), "r"(b[1]));
}

// ===========================================================================
// tf32 mma.sync GEMM body (unchanged from passing R9 kernel).
// FUSED=1: blockIdx.z selects (A,C,bias) triple; head-split out.
// ===========================================================================
template <int FUSED>
__global__ void __launch_bounds__(256) gemm_tf32_mma(
    const float* __restrict__ A0, const float* __restrict__ A1,
    const float* __restrict__ A2,
    const float* __restrict__ W0, const float* __restrict__ W1,
    const float* __restrict__ W2,
    const float* __restrict__ b0, const float* __restrict__ b1,
    const float* __restrict__ b2,
    float* __restrict__ C0, float* __restrict__ C1, float* __restrict__ C2)
{
    __shared__ uint32_t sA[2][16 * SW];
    __shared__ uint32_t sB[2][16 * SW];

    const int z = FUSED ? blockIdx.z : 0;
    const float* A    = (z == 0) ? A0 : (z == 1) ? A1 : A2;
    const float* Bw   = (z == 0) ? W0 : (z == 1) ? W1 : W2;
    const float* bias = (z == 0) ? b0 : (z == 1) ? b1 : b2;
    float*       C    = (z == 0) ? C0 : (z == 1) ? C1 : C2;

    const int t  = threadIdx.x;
    const int bm = blockIdx.y * 128;
    const int bn = blockIdx.x * 128;

    const int lm = t >> 1;
    const int kq = (t & 1) * 8;
    const float* Ap = A  + (size_t)(bm + lm) * EMB + kq;
    const float* Bp = Bw + (size_t)(bn + lm) * EMB + kq;

    const int wid  = t >> 5, lane = t & 31;
    const int q    = lane & 3, g = lane >> 2;
    const int wm   = (wid & 1) * 64;
    const int wn   = (wid >> 1) * 32;

    float acc[4][4][4] = {};

    auto stage = [&](int buf, float4 a0, float4 a1, float4 v0, float4 v1) {
        uint32_t* pa = &sA[buf][lm];
        uint32_t* pb = &sB[buf][lm];
        pa[(kq+0)*SW] = f2tf32(a0.x); pa[(kq+1)*SW] = f2tf32(a0.y);
        pa[(kq+2)*SW] = f2tf32(a0.z); pa[(kq+3)*SW] = f2tf32(a0.w);
        pa[(kq+4)*SW] = f2tf32(a1.x); pa[(kq+5)*SW] = f2tf32(a1.y);
        pa[(kq+6)*SW] = f2tf32(a1.z); pa[(kq+7)*SW] = f2tf32(a1.w);
        pb[(kq+0)*SW] = f2tf32(v0.x); pb[(kq+1)*SW] = f2tf32(v0.y);
        pb[(kq+2)*SW] = f2tf32(v0.z); pb[(kq+3)*SW] = f2tf32(v0.w);
        pb[(kq+4)*SW] = f2tf32(v1.x); pb[(kq+5)*SW] = f2tf32(v1.y);
        pb[(kq+6)*SW] = f2tf32(v1.z); pb[(kq+7)*SW] = f2tf32(v1.w);
    };

    {
        float4 a0 = *(const float4*)(Ap + 0), a1 = *(const float4*)(Ap + 4);
        float4 v0 = *(const float4*)(Bp + 0), v1 = *(const float4*)(Bp + 4);
        stage(0, a0, a1, v0, v1);
    }
    __syncthreads();

    int buf = 0;
    for (int c = 0; c < EMB / 16; ++c) {
        float4 na0, na1, nb0, nb1;
        const bool more = (c + 1) < EMB / 16;
        if (more) {
            const int k0 = (c + 1) * 16;
            na0 = *(const float4*)(Ap + k0 + 0); na1 = *(const float4*)(Ap + k0 + 4);
            nb0 = *(const float4*)(Bp + k0 + 0); nb1 = *(const float4*)(Bp + k0 + 4);
        }

        #pragma unroll
        for (int ks = 0; ks < 16; ks += 8) {
            const uint32_t* paq  = &sA[buf][(ks + q    ) * SW];
            const uint32_t* paq4 = &sA[buf][(ks + q + 4) * SW];
            const uint32_t* pbq  = &sB[buf][(ks + q    ) * SW];
            const uint32_t* pbq4 = &sB[buf][(ks + q + 4) * SW];

            uint32_t af[4][4], bf[4][2];
            #pragma unroll
            for (int tm = 0; tm < 4; ++tm) {
                const int mo = wm + tm * 16 + g;
                af[tm][0] = paq [mo];     af[tm][1] = paq [mo + 8];
                af[tm][2] = paq4[mo];     af[tm][3] = paq4[mo + 8];
            }
            #pragma unroll
            for (int tn = 0; tn < 4; ++tn) {
                const int no = wn + tn * 8 + g;
                bf[tn][0] = pbq [no];     bf[tn][1] = pbq4[no];
            }
            #pragma unroll
            for (int tm = 0; tm < 4; ++tm)
                #pragma unroll
                for (int tn = 0; tn < 4; ++tn)
                    mma_tf32(acc[tm][tn], af[tm], bf[tn]);
        }

        if (more) {
            stage(buf ^ 1, na0, na1, nb0, nb1);
            __syncthreads();
            buf ^= 1;
        }
    }

    #pragma unroll
    for (int tm = 0; tm < 4; ++tm) {
        const int r0 = bm + wm + tm * 16 + g;
        #pragma unroll
        for (int tn = 0; tn < 4; ++tn) {
            const int n  = bn + wn + tn * 8 + 2 * q;
            const float bx = bias[n], by = bias[n + 1];
            float2 v0 = make_float2(acc[tm][tn][0] + bx, acc[tm][tn][1] + by);
            float2 v1 = make_float2(acc[tm][tn][2] + bx, acc[tm][tn][3] + by);
            if (FUSED == 0) {
                *(float2*)&C[(size_t)r0      * EMB + n] = v0;
                *(float2*)&C[(size_t)(r0+8)  * EMB + n] = v1;
            } else {
                const int h_ = n >> 6, d_ = n & (HD - 1);
                {
                    const int b_ = r0 >> 11, s_ = r0 & (SEQ - 1);
                    *(float2*)&C[((((size_t)b_ * NH + h_) * SEQ + s_) << 6) + d_] = v0;
                }
                {
                    const int r1 = r0 + 8;
                    const int b_ = r1 >> 11, s_ = r1 & (SEQ - 1);
                    *(float2*)&C[((((size_t)b_ * NH + h_) * SEQ + s_) << 6) + d_] = v1;
                }
            }
        }
    }
}

// ===========================================================================
// tf32 mma.sync flash attention, causal.
// CTA: 128 Q rows x 32-key KV blocks. 256 thr = 8 warps; warp tile = 16 rows
// x full width (softmax rows stay inside one warp; row-reduce = 2 shuffles).
// Q frags preloaded to registers (scaled 0.125, rna-tf32). K/V staged to smem
// as tf32 (pads 68/72 words -> conflict-free b-frags). P (exp scores, tf32)
// round-trips through sP (pad 36 -> conflict-free a-frags). 3 bars/iter.
// ===========================================================================
#define QT_ROWS 128
#define KT      32

__global__ void __launch_bounds__(256, 2) flash_attn_mma(
    const float* __restrict__ Q, const float* __restrict__ K,
    const float* __restrict__ V, float* __restrict__ ctx)
{
    __shared__ uint32_t sK[KT * 68];        // [key][d]   8704 B
    __shared__ uint32_t sV[KT * 72];        // [key][d]   9216 B
    __shared__ uint32_t sP[QT_ROWS * 36];   // [row][key] 18432 B

    const int t  = threadIdx.x;
    const int qt = (SEQ / QT_ROWS - 1) - blockIdx.x;   // longest first
    const int bh = blockIdx.y;
    const int b_ = bh >> 4, h_ = bh & (NH - 1);

    const int wid = t >> 5, lane = t & 31;
    const int g = lane >> 2, q = lane & 3;
    const int m0 = wid * 16;
    const int qbase = qt * QT_ROWS;
    const int grA = qbase + m0 + g;         // global row (lane rows: grA, grA+8)
    const int grB = grA + 8;

    // ---- preload Q fragments (once), scaled by 1/sqrt(64)=0.125, tf32 ----
    const float* Qb = Q + ((size_t)bh * SEQ + qbase + m0) * HD;
    uint32_t qf[8][4];
    #pragma unroll
    for (int ks = 0; ks < 8; ks++) {
        qf[ks][0] = f2tf32(Qb[(g    ) * HD + ks * 8 + q    ] * 0.125f);
        qf[ks][1] = f2tf32(Qb[(g + 8) * HD + ks * 8 + q    ] * 0.125f);
        qf[ks][2] = f2tf32(Qb[(g    ) * HD + ks * 8 + q + 4] * 0.125f);
        qf[ks][3] = f2tf32(Qb[(g + 8) * HD + ks * 8 + q + 4] * 0.125f);
    }

    // loader mapping: 8 threads per key row, 8 floats each
    const int lkey = t >> 3;
    const int ldc  = (t & 7) * 8;

    float mA = -CUDART_INF_F, mB = -CUDART_INF_F;
    float lA = 0.f, lB = 0.f;
    float o[8][4] = {};                     // O warp tile 16x64 (8 n-tiles)

    const int jt_max = 4 * qt + 3;          // KV covers [0, (qt+1)*128)
    for (int jt = 0; jt <= jt_max; jt++) {
        const int jtb = jt * KT;
        const float* Kg = K + ((size_t)bh * SEQ + jtb) * HD;
        const float* Vg = V + ((size_t)bh * SEQ + jtb) * HD;

        __syncthreads();                    // prev iter's readers done
        {
            float4 k0 = *(const float4*)(Kg + lkey * HD + ldc);
            float4 k1 = *(const float4*)(Kg + lkey * HD + ldc + 4);
            float4 v0 = *(const float4*)(Vg + lkey * HD + ldc);
            float4 v1 = *(const float4*)(Vg + lkey * HD + ldc + 4);
            uint4 ku0 = make_uint4(f2tf32(k0.x), f2tf32(k0.y), f2tf32(k0.z), f2tf32(k0.w));
            uint4 ku1 = make_uint4(f2tf32(k1.x), f2tf32(k1.y), f2tf32(k1.z), f2tf32(k1.w));
            uint4 vu0 = make_uint4(f2tf32(v0.x), f2tf32(v0.y), f2tf32(v0.z), f2tf32(v0.w));
            uint4 vu1 = make_uint4(f2tf32(v1.x), f2tf32(v1.y), f2tf32(v1.z), f2tf32(v1.w));
            *(uint4*)&sK[lkey * 68 + ldc    ] = ku0;
            *(uint4*)&sK[lkey * 68 + ldc + 4] = ku1;
            *(uint4*)&sV[lkey * 72 + ldc    ] = vu0;
            *(uint4*)&sV[lkey * 72 + ldc + 4] = vu1;
        }
        __syncthreads();                    // K,V tiles ready

        // ---- S = (Q/8) * K^T : warp tile 16x32, 4 n-tiles, 8 k-steps ----
        float s_[4][4] = {};
        #pragma unroll
        for (int ks = 0; ks < 8; ks++) {
            #pragma unroll
            for (int tn = 0; tn < 4; tn++) {
                uint32_t bfr[2];
                bfr[0] = sK[(tn * 8 + g) * 68 + ks * 8 + q    ];
                bfr[1] = sK[(tn * 8 + g) * 68 + ks * 8 + q + 4];
                mma_tf32(s_[tn], qf[ks], bfr);
            }
        }

        // ---- causal mask + online softmax (rows grA, grB per lane) ----
        float nmA = -CUDART_INF_F, nmB = -CUDART_INF_F;
        #pragma unroll
        for (int tn = 0; tn < 4; tn++) {
            const int colb = jtb + tn * 8 + 2 * q;
            if (colb     > grA) s_[tn][0] = -CUDART_INF_F;
            if (colb + 1 > grA) s_[tn][1] = -CUDART_INF_F;
            if (colb     > grB) s_[tn][2] = -CUDART_INF_F;
            if (colb + 1 > grB) s_[tn][3] = -CUDART_INF_F;
            nmA = fmaxf(nmA, fmaxf(s_[tn][0], s_[tn][1]));
            nmB = fmaxf(nmB, fmaxf(s_[tn][2], s_[tn][3]));
        }
        nmA = fmaxf(nmA, __shfl_xor_sync(0xffffffffu, nmA, 1, 4));
        nmA = fmaxf(nmA, __shfl_xor_sync(0xffffffffu, nmA, 2, 4));
        nmB = fmaxf(nmB, __shfl_xor_sync(0xffffffffu, nmB, 1, 4));
        nmB = fmaxf(nmB, __shfl_xor_sync(0xffffffffu, nmB, 2, 4));

        const float mAn = fmaxf(mA, nmA), mBn = fmaxf(mB, nmB);
        const float rA = __expf(mA - mAn), rB = __expf(mB - mBn);
        mA = mAn; mB = mBn;

        float sumA = 0.f, sumB = 0.f;
        float pv[4][4];
        #pragma unroll
        for (int tn = 0; tn < 4; tn++) {
            pv[tn][0] = __expf(s_[tn][0] - mAn);
            pv[tn][1] = __expf(s_[tn][1] - mAn);
            pv[tn][2] = __expf(s_[tn][2] - mBn);
            pv[tn][3] = __expf(s_[tn][3] - mBn);
            sumA += pv[tn][0] + pv[tn][1];
            sumB += pv[tn][2] + pv[tn][3];
        }
        sumA += __shfl_xor_sync(0xffffffffu, sumA, 1, 4);
        sumA += __shfl_xor_sync(0xffffffffu, sumA, 2, 4);
        sumB += __shfl_xor_sync(0xffffffffu, sumB, 1, 4);
        sumB += __shfl_xor_sync(0xffffffffu, sumB, 2, 4);
        lA = lA * rA + sumA;
        lB = lB * rB + sumB;
        #pragma unroll
        for (int tn = 0; tn < 8; tn++) {
            o[tn][0] *= rA; o[tn][1] *= rA;
            o[tn][2] *= rB; o[tn][3] *= rB;
        }

        __syncthreads();                    // (reuse ordering: P after S reads)
        #pragma unroll
        for (int tn = 0; tn < 4; tn++) {
            *(uint2*)&sP[(m0 + g    ) * 36 + tn * 8 + 2 * q] =
                make_uint2(f2tf32(pv[tn][0]), f2tf32(pv[tn][1]));
            *(uint2*)&sP[(m0 + g + 8) * 36 + tn * 8 + 2 * q] =
                make_uint2(f2tf32(pv[tn][2]), f2tf32(pv[tn][3]));
        }
        __syncthreads();                    // P tile ready

        // ---- O += P * V : warp tile 16x64, 8 n-tiles(d), 4 k-steps(key) ----
        #pragma unroll
        for (int ks = 0; ks < 4; ks++) {
            uint32_t af[4];
            af[0] = sP[(m0 + g    ) * 36 + ks * 8 + q    ];
            af[1] = sP[(m0 + g + 8) * 36 + ks * 8 + q    ];
            af[2] = sP[(m0 + g    ) * 36 + ks * 8 + q + 4];
            af[3] = sP[(m0 + g + 8) * 36 + ks * 8 + q + 4];
            #pragma unroll
            for (int tn = 0; tn < 8; tn++) {
                uint32_t bfr[2];
                bfr[0] = sV[(ks * 8 + q    ) * 72 + tn * 8 + g];
                bfr[1] = sV[(ks * 8 + q + 4) * 72 + tn * 8 + g];
                mma_tf32(o[tn], af, bfr);
            }
        }
    }

    // ---- epilogue: normalize, write ctx (B,S,E) ----
    const float iA = 1.f / lA, iB = 1.f / lB;
    float* ctxA = ctx + ((size_t)b_ * SEQ + grA) * EMB + h_ * HD;
    float* ctxB = ctx + ((size_t)b_ * SEQ + grB) * EMB + h_ * HD;
    #pragma unroll
    for (int tn = 0; tn < 8; tn++) {
        const int d0 = tn * 8 + 2 * q;
        *(float2*)(ctxA + d0) = make_float2(o[tn][0] * iA, o[tn][1] * iA);
        *(float2*)(ctxB + d0) = make_float2(o[tn][2] * iB, o[tn][3] * iB);
    }
}

// ---------------------------------------------------------------------------
extern "C" void kernel_launch(void* const* d_in, const int* in_sizes, int n_in,
                              void* d_out, int out_size)
{
    (void)in_sizes; (void)n_in; (void)out_size;
    const float* query = (const float*)d_in[0];
    const float* key   = (const float*)d_in[1];
    const float* value = (const float*)d_in[2];
    // d_in[3] = attn_mask (causal triu) — baked into the flash kernel
    const float* q_w = (const float*)d_in[4];
    const float* q_b = (const float*)d_in[5];
    const float* k_w = (const float*)d_in[6];
    const float* k_b = (const float*)d_in[7];
    const float* v_w = (const float*)d_in[8];
    const float* v_b = (const float*)d_in[9];
    const float* o_w = (const float*)d_in[10];
    const float* o_b = (const float*)d_in[11];

    float *gq, *gk, *gv, *gctx;
    cudaGetSymbolAddress((void**)&gq,   g_q);
    cudaGetSymbolAddress((void**)&gk,   g_k);
    cudaGetSymbolAddress((void**)&gv,   g_v);
    cudaGetSymbolAddress((void**)&gctx, g_ctx);

    // fused Q/K/V projections: one launch, 3x grid depth
    gemm_tf32_mma<1><<<dim3(EMB / 128, MROWS / 128, 3), 256>>>(
        query, key, value,
        q_w, k_w, v_w,
        q_b, k_b, v_b,
        gq, gk, gv);

    flash_attn_mma<<<dim3(SEQ / QT_ROWS, BD * NH), 256>>>(gq, gk, gv, gctx);

    gemm_tf32_mma<0><<<dim3(EMB / 128, MROWS / 128, 1), 256>>>(
        gctx, nullptr, nullptr,
        o_w, nullptr, nullptr,
        o_b, nullptr, nullptr,
        (float*)d_out, nullptr, nullptr);
}